// round 3
// baseline (speedup 1.0000x reference)
#include <cuda_runtime.h>
#include <cuda_bf16.h>
#include <math.h>

// ---------------- problem constants ----------------
#define FH 200
#define FW 272
#define HW 54400          // FH*FW
#define CIN 256
#define COUT 256
#define KDIM 2304         // 9*256
#define NANCH 489600      // HW*9
#define PRE_NMS 6000
#define POST_NMS 1000
#define NWORDS 94         // ceil(6000/64)
#define CAND_CAP 16384

// ---------------- scratch (device globals; no allocation allowed) ----------------
__device__ float g_wt[KDIM * COUT];                 // transposed weights [k][co]
__device__ float g_relu[COUT * HW];                 // conv1+relu output  [co][px]
__device__ unsigned g_key[NANCH];                   // sortable conf keys (coarse fp32)
__device__ float4 g_offs[NANCH];                    // reg deltas per anchor
__device__ unsigned g_hist[65536];
__device__ unsigned g_thresh;
__device__ unsigned g_candCount;
__device__ unsigned long long g_cand[CAND_CAP];
__device__ unsigned g_topIdx[PRE_NMS];
__device__ float4 g_boxes[PRE_NMS + 64];
__device__ unsigned long long g_validw[96];
__device__ unsigned long long g_sup[(size_t)PRE_NMS * NWORDS];
__device__ unsigned long long g_keepw[96];

// ---------------- helpers ----------------
__device__ __forceinline__ unsigned f2k(float f) {
    unsigned b = __float_as_uint(f);
    return (b & 0x80000000u) ? ~b : (b | 0x80000000u);
}

#define PK(p, lo, hi) asm("mov.b64 %0, {%1,%2};" : "=l"(p) : "f"(lo), "f"(hi))
#define UNPK(lo, hi, p) asm("mov.b64 {%0,%1}, %2;" : "=f"(lo), "=f"(hi) : "l"(p))
#define FMA2(d, a, b, c) asm("fma.rn.f32x2 %0, %1, %2, %3;" : "=l"(d) : "l"(a), "l"(b), "l"(c))
#define ADD2(d, a, b) asm("add.rn.f32x2 %0, %1, %2;" : "=l"(d) : "l"(a), "l"(b))

// ---------------- K0: zero scratch ----------------
__global__ void k_zero() {
    unsigned i = blockIdx.x * 256u + threadIdx.x;
    if (i < 65536u) g_hist[i] = 0u;
    if (i < 96u) g_validw[i] = 0ull;
    if (i == 0u) { g_candCount = 0u; g_thresh = 0u; }
}

// ---------------- K0b: transpose conv1 weights to [k= tap*256+ci][co] ----------------
__global__ void k_wt(const float* __restrict__ w1) {
    int k = blockIdx.x;          // 0..2303
    int co = threadIdx.x;        // 0..255
    int tap = k >> 8;
    int ci = k & 255;
    g_wt[(size_t)k * COUT + co] = w1[((size_t)co * 256 + ci) * 9 + tap];
}

// ---------------- conv1: implicit GEMM, fp32x2 FMA, per-stage partial accumulation ----
// grid (425 px-blocks, 2 co-blocks), 512 threads, BM(co)=128 BN(px)=128 BK=16
// thread frag: 4 co x 8 px. Per-stage partial then one packed add -> 4x lower
// accumulation error than a single 2304-long chain.
__global__ __launch_bounds__(512, 1) void k_conv1(const float* __restrict__ x,
                                                  const float* __restrict__ b1) {
    __shared__ __align__(16) float As[2][16][128];
    __shared__ __align__(16) float Bs[2][16][128];

    const int tid = threadIdx.x;
    const int px0 = blockIdx.x * 128;
    const int co0 = blockIdx.y * 128;
    const int lane = tid & 127;     // loader column (px for B, co for A)
    const int kq = tid >> 7;        // loader k-row base 0..3 (rows kq+4u)
    const int px = px0 + lane;
    const int py = px / FW;
    const int pxx = px - py * FW;
    const int ty = tid >> 4;        // 0..31 -> co frag (4 co)
    const int tx = tid & 15;        // 0..15 -> px frag (8 px = 4 pairs)

    unsigned long long acc[4][4];
#pragma unroll
    for (int i = 0; i < 4; ++i)
#pragma unroll
        for (int j = 0; j < 4; ++j) acc[i][j] = 0ull;

    float ra[4], rb[4];

    auto ldStage = [&](int s) {
        int tap = s >> 4;
        int ci = ((s & 15) << 4) + kq;
        int t3 = tap / 3;
        int dy = t3 - 1;
        int dx = (tap - t3 * 3) - 1;
        int yy = py + dy, xx = pxx + dx;
        bool v = ((unsigned)yy < (unsigned)FH) && ((unsigned)xx < (unsigned)FW);
        const float* bp = x + (size_t)ci * HW + yy * FW + xx;
        const float* ap = g_wt + ((size_t)(tap * 256 + ci)) * COUT + co0 + lane;
#pragma unroll
        for (int u = 0; u < 4; ++u) {
            rb[u] = v ? __ldg(bp + (size_t)(4 * u) * HW) : 0.0f;
            ra[u] = __ldg(ap + 4 * u * COUT);
        }
    };
    auto stStage = [&](int buf) {
#pragma unroll
        for (int u = 0; u < 4; ++u) {
            As[buf][kq + 4 * u][lane] = ra[u];
            Bs[buf][kq + 4 * u][lane] = rb[u];
        }
    };

    ldStage(0);
    stStage(0);
    __syncthreads();

    int cur = 0;
    for (int s = 0; s < 144; ++s) {
        if (s + 1 < 144) ldStage(s + 1);

        unsigned long long par[4][4];
#pragma unroll
        for (int i = 0; i < 4; ++i)
#pragma unroll
            for (int j = 0; j < 4; ++j) par[i][j] = 0ull;

#pragma unroll
        for (int kk = 0; kk < 16; ++kk) {
            float4 a4 = *(const float4*)(&As[cur][kk][ty * 4]);
            float4 q0 = *(const float4*)(&Bs[cur][kk][tx * 8]);
            float4 q1 = *(const float4*)(&Bs[cur][kk][tx * 8 + 4]);
            unsigned long long pb0, pb1, pb2, pb3;
            PK(pb0, q0.x, q0.y); PK(pb1, q0.z, q0.w);
            PK(pb2, q1.x, q1.y); PK(pb3, q1.z, q1.w);
            float av[4] = {a4.x, a4.y, a4.z, a4.w};
#pragma unroll
            for (int i = 0; i < 4; ++i) {
                unsigned long long pa;
                PK(pa, av[i], av[i]);
                FMA2(par[i][0], pa, pb0, par[i][0]);
                FMA2(par[i][1], pa, pb1, par[i][1]);
                FMA2(par[i][2], pa, pb2, par[i][2]);
                FMA2(par[i][3], pa, pb3, par[i][3]);
            }
        }
#pragma unroll
        for (int i = 0; i < 4; ++i)
#pragma unroll
            for (int j = 0; j < 4; ++j) ADD2(acc[i][j], acc[i][j], par[i][j]);

        if (s + 1 < 144) stStage(cur ^ 1);
        __syncthreads();
        cur ^= 1;
    }

    // epilogue: bias + relu + store
#pragma unroll
    for (int i = 0; i < 4; ++i) {
        int co = co0 + ty * 4 + i;
        float bias = __ldg(b1 + co);
        float* orow = g_relu + (size_t)co * HW + px0 + tx * 8;
#pragma unroll
        for (int j = 0; j < 4; ++j) {
            float lo, hi;
            UNPK(lo, hi, acc[i][j]);
            lo = fmaxf(__fadd_rn(lo, bias), 0.0f);
            hi = fmaxf(__fadd_rn(hi, bias), 0.0f);
            float2 st; st.x = lo; st.y = hi;
            *(float2*)(orow + 2 * j) = st;
        }
    }
}

// ---------------- conv2: 1x1 convs (45 outputs) + coarse keys + histogram ----------------
__global__ __launch_bounds__(128) void k_conv2(const float* __restrict__ wcls,
                                               const float* __restrict__ bcls,
                                               const float* __restrict__ wreg,
                                               const float* __restrict__ breg) {
    __shared__ float Ws[45 * 256];
    int tid = threadIdx.x;
    for (int i = tid; i < 45 * 256; i += 128) {
        int o = i >> 8, c = i & 255;
        Ws[i] = (o < 9) ? wcls[o * 256 + c] : wreg[(o - 9) * 256 + c];
    }
    __syncthreads();

    int px = blockIdx.x * 128 + tid;
    float acc[45];
#pragma unroll
    for (int o = 0; o < 45; ++o) acc[o] = 0.0f;

    const float* rp = g_relu + px;
#pragma unroll 2
    for (int c = 0; c < 256; ++c) {
        float v = __ldg(rp + (size_t)c * HW);
        const float* w = Ws + c;
#pragma unroll
        for (int o = 0; o < 45; ++o) acc[o] = fmaf(w[o * 256], v, acc[o]);
    }

    int p9 = px * 9;
#pragma unroll
    for (int a = 0; a < 9; ++a) {
        float cf = acc[a] + __ldg(bcls + a);
        unsigned key = f2k(cf);
        g_key[p9 + a] = key;
        atomicAdd(&g_hist[key >> 16], 1u);
        float4 o4;
        o4.x = __fadd_rn(acc[9 + a * 4 + 0], __ldg(breg + a * 4 + 0));
        o4.y = __fadd_rn(acc[9 + a * 4 + 1], __ldg(breg + a * 4 + 1));
        o4.z = __fadd_rn(acc[9 + a * 4 + 2], __ldg(breg + a * 4 + 2));
        o4.w = __fadd_rn(acc[9 + a * 4 + 3], __ldg(breg + a * 4 + 3));
        g_offs[p9 + a] = o4;
    }
}

// ---------------- threshold bin from histogram ----------------
__global__ void k_thresh() {
    __shared__ unsigned csum[1024];
    int t = threadIdx.x;
    unsigned mysum = 0;
    for (int b = 0; b < 64; ++b) mysum += g_hist[t * 64 + b];
    csum[t] = mysum;
    __syncthreads();
    for (int off = 1; off < 1024; off <<= 1) {
        unsigned v = (t + off < 1024) ? csum[t + off] : 0u;
        __syncthreads();
        csum[t] += v;
        __syncthreads();
    }
    unsigned run = csum[t] - mysum;  // count of keys in bins >= (t+1)*64
    for (int b = 63; b >= 0; --b) {
        unsigned h = g_hist[t * 64 + b];
        run += h;
        if (run >= PRE_NMS && (run - h) < PRE_NMS) g_thresh = (unsigned)(t * 64 + b);
    }
}

// ---------------- collect candidates (superset of true top-6000) ----------------
__global__ void k_collect() {
    unsigned i = blockIdx.x * 256u + threadIdx.x;
    if (i >= NANCH) return;
    unsigned key = g_key[i];
    if ((key >> 16) >= g_thresh) {
        unsigned p = atomicAdd(&g_candCount, 1u);
        if (p < CAND_CAP)
            g_cand[p] = ((unsigned long long)key << 32) | (unsigned)(~i);
    }
}

// ---------------- rescore candidates in fp64 (one warp per candidate) ----------------
__global__ __launch_bounds__(256) void k_rescore(const float* __restrict__ wcls,
                                                 const float* __restrict__ bcls) {
    unsigned n = g_candCount;
    if (n > CAND_CAP) n = CAND_CAP;
    unsigned p = blockIdx.x * 8u + (threadIdx.x >> 5);
    if (p >= n) return;
    int lid = threadIdx.x & 31;
    unsigned long long e = g_cand[p];
    unsigned idx = ~((unsigned)(e & 0xffffffffull));
    int a = idx % 9;
    int px = idx / 9;
    const float* wrow = wcls + a * 256;
    const float* rp = g_relu + px;
    double s = 0.0;
#pragma unroll
    for (int u = 0; u < 8; ++u) {
        int c = lid * 8 + u;
        s += (double)__ldg(wrow + c) * (double)__ldg(rp + (size_t)c * HW);
    }
#pragma unroll
    for (int off = 16; off > 0; off >>= 1)
        s += __shfl_down_sync(0xffffffffu, s, off);
    if (lid == 0) {
        s += (double)__ldg(bcls + a);
        unsigned key = f2k((float)s);
        g_cand[p] = ((unsigned long long)key << 32) | (unsigned)(~idx);
    }
}

// ---------------- single-block bitonic sort (descending) ----------------
__global__ void k_sort() {
    extern __shared__ unsigned long long ss[];
    int tid = threadIdx.x;
    unsigned n = g_candCount;
    if (n > CAND_CAP) n = CAND_CAP;
    for (int i = tid; i < CAND_CAP; i += 1024) ss[i] = (i < (int)n) ? g_cand[i] : 0ull;
    __syncthreads();
    for (unsigned k = 2; k <= (unsigned)CAND_CAP; k <<= 1) {
        for (unsigned j = k >> 1; j > 0; j >>= 1) {
            for (unsigned i = tid; i < (unsigned)CAND_CAP; i += 1024) {
                unsigned ixj = i ^ j;
                if (ixj > i) {
                    unsigned long long a = ss[i], b = ss[ixj];
                    bool sw = ((i & k) == 0u) ? (a < b) : (a > b);
                    if (sw) { ss[i] = b; ss[ixj] = a; }
                }
            }
            __syncthreads();
        }
    }
    for (int r = tid; r < PRE_NMS; r += 1024)
        g_topIdx[r] = ~((unsigned)(ss[r] & 0xffffffffull));
}

// ---------------- decode + clip + valid (no FMA contraction) ----------------
__global__ void k_decode(const int* __restrict__ imh, const int* __restrict__ imw) {
    int r = blockIdx.x * 256 + threadIdx.x;
    if (r >= PRE_NMS) return;
    unsigned idx = g_topIdx[r];
    int a = idx % 9;
    int p = idx / 9;
    int xx = p % FW;
    int yy = p / FW;
    int si = a / 3, ri = a - si * 3;
    double sc = (double)(32 << si);
    double rr = (ri == 0) ? 0.5 : ((ri == 1) ? 1.0 : 2.0);
    float hw = (float)(sc * sqrt(1.0 / rr) * 0.5);
    float hh = (float)(sc * sqrt(rr) * 0.5);
    float cx0 = __fmul_rn(__fadd_rn((float)xx, 0.5f), 4.0f);
    float cy0 = __fmul_rn(__fadd_rn((float)yy, 0.5f), 4.0f);
    float x1a = __fsub_rn(cx0, hw), x2a = __fadd_rn(cx0, hw);
    float y1a = __fsub_rn(cy0, hh), y2a = __fadd_rn(cy0, hh);
    float wa = __fsub_rn(x2a, x1a), ha = __fsub_rn(y2a, y1a);
    float cxa = __fadd_rn(x1a, __fmul_rn(0.5f, wa));
    float cya = __fadd_rn(y1a, __fmul_rn(0.5f, ha));
    float4 d = g_offs[idx];
    float cx = __fadd_rn(__fmul_rn(d.x, wa), cxa);
    float cy = __fadd_rn(__fmul_rn(d.y, ha), cya);
    float w = __fmul_rn(expf(d.z), wa);
    float h = __fmul_rn(expf(d.w), ha);
    float bw = (float)__ldg(imw);
    float bh = (float)__ldg(imh);
    float x1 = fminf(fmaxf(__fsub_rn(cx, __fmul_rn(0.5f, w)), 0.0f), bw);
    float y1 = fminf(fmaxf(__fsub_rn(cy, __fmul_rn(0.5f, h)), 0.0f), bh);
    float x2 = fminf(fmaxf(__fadd_rn(cx, __fmul_rn(0.5f, w)), 0.0f), bw);
    float y2 = fminf(fmaxf(__fadd_rn(cy, __fmul_rn(0.5f, h)), 0.0f), bh);
    float4 b; b.x = x1; b.y = y1; b.z = x2; b.w = y2;
    g_boxes[r] = b;
    bool valid = (__fsub_rn(x2, x1) >= 1.0f) && (__fsub_rn(y2, y1) >= 1.0f);
    if (valid) atomicOr(&g_validw[r >> 6], 1ull << (r & 63));
}

// ---------------- suppression bitmask matrix (no FMA contraction) ----------------
__global__ void k_sup() {
    __shared__ float4 bj[64];
    int t = threadIdx.x;
    int bjx = blockIdx.y;
    int j0 = bjx * 64;
    {
        int j = j0 + t;
        bj[t] = (j < PRE_NMS) ? g_boxes[j] : make_float4(0.f, 0.f, 0.f, 0.f);
    }
    __syncthreads();
    int i = blockIdx.x * 64 + t;
    if (i >= PRE_NMS) return;
    float4 A = g_boxes[i];
    float areaA = __fmul_rn(__fsub_rn(A.z, A.x), __fsub_rn(A.w, A.y));
    unsigned long long bits = 0ull;
    int jmax = PRE_NMS - j0;
    if (jmax > 64) jmax = 64;
    for (int jj = 0; jj < jmax; ++jj) {
        float4 B = bj[jj];
        float areaB = __fmul_rn(__fsub_rn(B.z, B.x), __fsub_rn(B.w, B.y));
        float lx = fmaxf(A.x, B.x), ly = fmaxf(A.y, B.y);
        float rx = fminf(A.z, B.z), ry = fminf(A.w, B.w);
        float iw = fmaxf(__fsub_rn(rx, lx), 0.0f);
        float ih = fmaxf(__fsub_rn(ry, ly), 0.0f);
        float inter = __fmul_rn(iw, ih);
        float denom = __fadd_rn(__fsub_rn(__fadd_rn(areaA, areaB), inter), 1e-9f);
        float iou = __fdiv_rn(inter, denom);
        if (iou > 0.7f) bits |= (1ull << jj);
    }
    g_sup[(size_t)i * NWORDS + bjx] = bits;
}

// ---------------- serial greedy NMS scan (1 warp, ring prefetch) ----------------
__global__ void k_scan() {
    int t = threadIdx.x;  // 0..31
    unsigned long long k0 = 0, k1 = 0, k2 = 0;
    unsigned long long v0 = g_validw[t];
    unsigned long long v1 = g_validw[t + 32];
    unsigned long long v2 = (t < 30) ? g_validw[t + 64] : 0ull;
    unsigned long long b0[8], b1[8], b2[8];
#pragma unroll
    for (int r = 0; r < 8; ++r) {
        const unsigned long long* row = g_sup + (size_t)r * NWORDS;
        b0[r] = row[t];
        b1[r] = row[t + 32];
        b2[r] = (t < 30) ? row[t + 64] : 0ull;
    }
#pragma unroll 1
    for (int base = 0; base < PRE_NMS; base += 8) {
#pragma unroll
        for (int s = 0; s < 8; ++s) {
            int i = base + s;
            unsigned long long vv = (b0[s] & k0) | (b1[s] & k1) | (b2[s] & k2);
            unsigned bal = __ballot_sync(0xffffffffu, vv != 0ull);
            int wi = i >> 6;
            if (bal == 0u) {
                unsigned long long bit = 1ull << (i & 63);
                if (wi < 32) {
                    if (t == wi && (v0 & bit)) k0 |= bit;
                } else if (wi < 64) {
                    if (t == (wi - 32) && (v1 & bit)) k1 |= bit;
                } else {
                    if (t == (wi - 64) && (v2 & bit)) k2 |= bit;
                }
            }
            int nr = i + 8;
            if (nr < PRE_NMS) {
                const unsigned long long* row = g_sup + (size_t)nr * NWORDS;
                b0[s] = row[t];
                b1[s] = row[t + 32];
                b2[s] = (t < 30) ? row[t + 64] : 0ull;
            }
        }
    }
    g_keepw[t] = k0;
    g_keepw[t + 32] = k1;
    if (t < 30) g_keepw[t + 64] = k2;
}

// ---------------- compact kept boxes into output ----------------
__global__ void k_out(float* __restrict__ out) {
    __shared__ unsigned pref[NWORDS];
    int tid = threadIdx.x;
    for (int i = tid; i < POST_NMS * 4; i += 256) out[i] = 0.0f;
    if (tid == 0) {
        unsigned run = 0;
        for (int w = 0; w < NWORDS; ++w) {
            pref[w] = run;
            run += (unsigned)__popcll(g_keepw[w]);
        }
    }
    __syncthreads();
    for (int i = tid; i < PRE_NMS; i += 256) {
        unsigned long long kw = g_keepw[i >> 6];
        if ((kw >> (i & 63)) & 1ull) {
            unsigned long long below = (i & 63) ? (kw & ((1ull << (i & 63)) - 1ull)) : 0ull;
            unsigned rank = pref[i >> 6] + (unsigned)__popcll(below);
            if (rank < POST_NMS) {
                float4 b = g_boxes[i];
                out[rank * 4 + 0] = b.x;
                out[rank * 4 + 1] = b.y;
                out[rank * 4 + 2] = b.z;
                out[rank * 4 + 3] = b.w;
            }
        }
    }
}

// ---------------- launch ----------------
extern "C" void kernel_launch(void* const* d_in, const int* in_sizes, int n_in,
                              void* d_out, int out_size) {
    const float* feat = (const float*)d_in[0];
    const float* w1 = (const float*)d_in[1];
    const float* b1 = (const float*)d_in[2];
    const float* wcls = (const float*)d_in[3];
    const float* bcls = (const float*)d_in[4];
    const float* wreg = (const float*)d_in[5];
    const float* breg = (const float*)d_in[6];
    const int* imh = (const int*)d_in[7];
    const int* imw = (const int*)d_in[8];
    float* out = (float*)d_out;

    cudaFuncSetAttribute(k_sort, cudaFuncAttributeMaxDynamicSharedMemorySize, 131072);

    k_zero<<<257, 256>>>();
    k_wt<<<KDIM, 256>>>(w1);
    k_conv1<<<dim3(HW / 128, 2), 512>>>(feat, b1);
    k_conv2<<<HW / 128, 128>>>(wcls, bcls, wreg, breg);
    k_thresh<<<1, 1024>>>();
    k_collect<<<(NANCH + 255) / 256, 256>>>();
    k_rescore<<<CAND_CAP / 8, 256>>>(wcls, bcls);
    k_sort<<<1, 1024, 131072>>>();
    k_decode<<<(PRE_NMS + 255) / 256, 256>>>(imh, imw);
    k_sup<<<dim3(NWORDS, NWORDS), 64>>>();
    k_scan<<<1, 32>>>();
    k_out<<<1, 256>>>(out);
}

// round 4
// speedup vs baseline: 1.4163x; 1.4163x over previous
#include <cuda_runtime.h>
#include <cuda_bf16.h>
#include <math.h>

// ---------------- problem constants ----------------
#define FH 200
#define FW 272
#define HW 54400          // FH*FW
#define CIN 256
#define COUT 256
#define KDIM 2304         // 9*256
#define NANCH 489600      // HW*9
#define PRE_NMS 6000
#define POST_NMS 1000
#define NWORDS 94         // ceil(6000/64)
#define CAND_CAP 16384

// ---------------- scratch (device globals; no allocation allowed) ----------------
__device__ float g_wt[KDIM * COUT];                 // transposed weights [k][co]
__device__ float g_relu[COUT * HW];                 // conv1+relu output  [co][px]
__device__ unsigned g_key[NANCH];                   // sortable conf keys (coarse fp32)
__device__ float4 g_offs[NANCH];                    // reg deltas per anchor
__device__ unsigned g_hist[65536];
__device__ unsigned g_thresh;
__device__ unsigned g_candCount;
__device__ unsigned long long g_cand[CAND_CAP];
__device__ unsigned g_topIdx[PRE_NMS];
__device__ float4 g_boxes[PRE_NMS + 64];
__device__ unsigned long long g_validw[96];
__device__ unsigned long long g_sup[(size_t)PRE_NMS * NWORDS];
__device__ unsigned long long g_keepw[96];

// ---------------- helpers ----------------
__device__ __forceinline__ unsigned f2k(float f) {
    unsigned b = __float_as_uint(f);
    return (b & 0x80000000u) ? ~b : (b | 0x80000000u);
}

#define PK(p, lo, hi) asm("mov.b64 %0, {%1,%2};" : "=l"(p) : "f"(lo), "f"(hi))
#define UNPK(lo, hi, p) asm("mov.b64 {%0,%1}, %2;" : "=f"(lo), "=f"(hi) : "l"(p))
#define FMA2(d, a, b, c) asm("fma.rn.f32x2 %0, %1, %2, %3;" : "=l"(d) : "l"(a), "l"(b), "l"(c))
#define ADD2(d, a, b) asm("add.rn.f32x2 %0, %1, %2;" : "=l"(d) : "l"(a), "l"(b))

// ---------------- K0: zero scratch ----------------
__global__ void k_zero() {
    unsigned i = blockIdx.x * 256u + threadIdx.x;
    if (i < 65536u) g_hist[i] = 0u;
    if (i < 96u) g_validw[i] = 0ull;
    if (i == 0u) { g_candCount = 0u; g_thresh = 0u; }
}

// ---------------- K0b: transpose conv1 weights to [k= tap*256+ci][co] ----------------
__global__ void k_wt(const float* __restrict__ w1) {
    int k = blockIdx.x;          // 0..2303
    int co = threadIdx.x;        // 0..255
    int tap = k >> 8;
    int ci = k & 255;
    g_wt[(size_t)k * COUT + co] = w1[((size_t)co * 256 + ci) * 9 + tap];
}

// ---------------- conv1: implicit GEMM, fp32x2 FMA, co-packed operands ----------------
// grid (425 px-blocks, 4 co-blocks), 256 threads, BM(co)=64 BN(px)=128 BK=16
// thread frag: 8 co (4 packed pairs) x 4 px. A (co) is contiguous in shared ->
// ulonglong2 gives packed FMA2 operands with zero mov overhead; A address is
// warp-uniform -> LDS broadcast. Per-stage partial accumulation preserved
// (bitwise identical accumulation chains to the passing R3 kernel).
__global__ __launch_bounds__(256, 2) void k_conv1(const float* __restrict__ x,
                                                  const float* __restrict__ b1) {
    __shared__ __align__(16) float As[2][16][64];
    __shared__ __align__(16) float Bs[2][16][128];

    const int tid = threadIdx.x;
    const int px0 = blockIdx.x * 128;
    const int co0 = blockIdx.y * 64;

    // loader lanes
    const int laneB = tid & 127;    // px lane for B
    const int kq2 = tid >> 7;       // 0..1 (B rows kq2 + 2u)
    const int laneA = tid & 63;     // co lane for A
    const int kq4 = tid >> 6;       // 0..3 (A rows kq4 + 4u)
    const int pxl = px0 + laneB;
    const int pyl = pxl / FW;
    const int pxxl = pxl - pyl * FW;

    // compute lanes
    const int ty = tid >> 5;        // 0..7  -> co base ty*8 (warp-uniform)
    const int tx = tid & 31;        // 0..31 -> px base tx*4

    unsigned long long acc[4][4];   // [px][copair]
#pragma unroll
    for (int p = 0; p < 4; ++p)
#pragma unroll
        for (int j = 0; j < 4; ++j) acc[p][j] = 0ull;

    float ra[4], rb[8];

    auto ldStage = [&](int s) {
        int tap = s >> 4;
        int cibase = (s & 15) << 4;
        int t3 = tap / 3;
        int dy = t3 - 1;
        int dx = (tap - t3 * 3) - 1;
        int yy = pyl + dy, xx = pxxl + dx;
        bool v = ((unsigned)yy < (unsigned)FH) && ((unsigned)xx < (unsigned)FW);
        const float* bp = x + (size_t)(cibase + kq2) * HW + yy * FW + xx;
#pragma unroll
        for (int u = 0; u < 8; ++u)
            rb[u] = v ? __ldg(bp + (size_t)(2 * u) * HW) : 0.0f;
        const float* ap = g_wt + (size_t)(tap * 256 + cibase + kq4) * COUT + co0 + laneA;
#pragma unroll
        for (int u = 0; u < 4; ++u)
            ra[u] = __ldg(ap + 4 * u * COUT);
    };
    auto stStage = [&](int buf) {
#pragma unroll
        for (int u = 0; u < 8; ++u) Bs[buf][kq2 + 2 * u][laneB] = rb[u];
#pragma unroll
        for (int u = 0; u < 4; ++u) As[buf][kq4 + 4 * u][laneA] = ra[u];
    };

    ldStage(0);
    stStage(0);
    __syncthreads();

    int cur = 0;
    for (int s = 0; s < 144; ++s) {
        if (s + 1 < 144) ldStage(s + 1);

        unsigned long long par[4][4];
#pragma unroll
        for (int p = 0; p < 4; ++p)
#pragma unroll
            for (int j = 0; j < 4; ++j) par[p][j] = 0ull;

#pragma unroll
        for (int kk = 0; kk < 16; ++kk) {
            ulonglong2 w01 = *(const ulonglong2*)(&As[cur][kk][ty * 8]);
            ulonglong2 w23 = *(const ulonglong2*)(&As[cur][kk][ty * 8 + 4]);
            float4 vq = *(const float4*)(&Bs[cur][kk][tx * 4]);
            float vv[4] = {vq.x, vq.y, vq.z, vq.w};
#pragma unroll
            for (int p = 0; p < 4; ++p) {
                unsigned long long pv;
                PK(pv, vv[p], vv[p]);
                FMA2(par[p][0], w01.x, pv, par[p][0]);
                FMA2(par[p][1], w01.y, pv, par[p][1]);
                FMA2(par[p][2], w23.x, pv, par[p][2]);
                FMA2(par[p][3], w23.y, pv, par[p][3]);
            }
        }
#pragma unroll
        for (int p = 0; p < 4; ++p)
#pragma unroll
            for (int j = 0; j < 4; ++j) ADD2(acc[p][j], acc[p][j], par[p][j]);

        if (s + 1 < 144) stStage(cur ^ 1);
        __syncthreads();
        cur ^= 1;
    }

    // epilogue: bias + relu + store (float4 per co row of 4 px)
#pragma unroll
    for (int j = 0; j < 4; ++j) {
        float lo[4], hi[4];
#pragma unroll
        for (int p = 0; p < 4; ++p) UNPK(lo[p], hi[p], acc[p][j]);
        int coL = co0 + ty * 8 + 2 * j;
        float bL = __ldg(b1 + coL);
        float bH = __ldg(b1 + coL + 1);
        float4 oL, oH;
        oL.x = fmaxf(__fadd_rn(lo[0], bL), 0.0f);
        oL.y = fmaxf(__fadd_rn(lo[1], bL), 0.0f);
        oL.z = fmaxf(__fadd_rn(lo[2], bL), 0.0f);
        oL.w = fmaxf(__fadd_rn(lo[3], bL), 0.0f);
        oH.x = fmaxf(__fadd_rn(hi[0], bH), 0.0f);
        oH.y = fmaxf(__fadd_rn(hi[1], bH), 0.0f);
        oH.z = fmaxf(__fadd_rn(hi[2], bH), 0.0f);
        oH.w = fmaxf(__fadd_rn(hi[3], bH), 0.0f);
        *(float4*)(g_relu + (size_t)coL * HW + px0 + tx * 4) = oL;
        *(float4*)(g_relu + (size_t)(coL + 1) * HW + px0 + tx * 4) = oH;
    }
}

// ---------------- conv2: 1x1 convs (45 outputs), pair-packed weights + pipelined loads ----
__global__ __launch_bounds__(128) void k_conv2(const float* __restrict__ wcls,
                                               const float* __restrict__ bcls,
                                               const float* __restrict__ wreg,
                                               const float* __restrict__ breg) {
    __shared__ __align__(16) float Ws[256 * 48];   // [c][o], o padded 46->48
    int tid = threadIdx.x;
    for (int i = tid; i < 256 * 46; i += 128) {
        int c = i / 46, o = i - c * 46;
        float v = (o < 9) ? wcls[o * 256 + c]
                          : ((o < 45) ? wreg[(o - 9) * 256 + c] : 0.0f);
        Ws[c * 48 + o] = v;
    }
    __syncthreads();

    int px = blockIdx.x * 128 + tid;
    unsigned long long acc[23];
#pragma unroll
    for (int p = 0; p < 23; ++p) acc[p] = 0ull;

    const float* rp = g_relu + px;
    float vbuf[4];
#pragma unroll
    for (int u = 0; u < 4; ++u) vbuf[u] = __ldg(rp + (size_t)u * HW);

    for (int c0 = 0; c0 < 256; c0 += 4) {
        float vcur[4];
#pragma unroll
        for (int u = 0; u < 4; ++u) vcur[u] = vbuf[u];
        if (c0 + 4 < 256) {
#pragma unroll
            for (int u = 0; u < 4; ++u)
                vbuf[u] = __ldg(rp + (size_t)(c0 + 4 + u) * HW);
        }
#pragma unroll
        for (int u = 0; u < 4; ++u) {
            unsigned long long pv;
            PK(pv, vcur[u], vcur[u]);
            const unsigned long long* wp =
                (const unsigned long long*)(Ws + (c0 + u) * 48);
#pragma unroll
            for (int p = 0; p < 23; ++p) FMA2(acc[p], wp[p], pv, acc[p]);
        }
    }

    float f[46];
#pragma unroll
    for (int p = 0; p < 23; ++p) UNPK(f[2 * p], f[2 * p + 1], acc[p]);

    int p9 = px * 9;
#pragma unroll
    for (int a = 0; a < 9; ++a) {
        float cf = f[a] + __ldg(bcls + a);
        unsigned key = f2k(cf);
        g_key[p9 + a] = key;
        atomicAdd(&g_hist[key >> 16], 1u);
        float4 o4;
        o4.x = __fadd_rn(f[9 + a * 4 + 0], __ldg(breg + a * 4 + 0));
        o4.y = __fadd_rn(f[9 + a * 4 + 1], __ldg(breg + a * 4 + 1));
        o4.z = __fadd_rn(f[9 + a * 4 + 2], __ldg(breg + a * 4 + 2));
        o4.w = __fadd_rn(f[9 + a * 4 + 3], __ldg(breg + a * 4 + 3));
        g_offs[p9 + a] = o4;
    }
}

// ---------------- threshold bin from histogram ----------------
__global__ void k_thresh() {
    __shared__ unsigned csum[1024];
    int t = threadIdx.x;
    unsigned mysum = 0;
    for (int b = 0; b < 64; ++b) mysum += g_hist[t * 64 + b];
    csum[t] = mysum;
    __syncthreads();
    for (int off = 1; off < 1024; off <<= 1) {
        unsigned v = (t + off < 1024) ? csum[t + off] : 0u;
        __syncthreads();
        csum[t] += v;
        __syncthreads();
    }
    unsigned run = csum[t] - mysum;  // count of keys in bins >= (t+1)*64
    for (int b = 63; b >= 0; --b) {
        unsigned h = g_hist[t * 64 + b];
        run += h;
        if (run >= PRE_NMS && (run - h) < PRE_NMS) g_thresh = (unsigned)(t * 64 + b);
    }
}

// ---------------- collect candidates (superset of true top-6000) ----------------
__global__ void k_collect() {
    unsigned i = blockIdx.x * 256u + threadIdx.x;
    if (i >= NANCH) return;
    unsigned key = g_key[i];
    if ((key >> 16) >= g_thresh) {
        unsigned p = atomicAdd(&g_candCount, 1u);
        if (p < CAND_CAP)
            g_cand[p] = ((unsigned long long)key << 32) | (unsigned)(~i);
    }
}

// ---------------- rescore candidates in fp64 (one warp per candidate) ----------------
__global__ __launch_bounds__(256) void k_rescore(const float* __restrict__ wcls,
                                                 const float* __restrict__ bcls) {
    unsigned n = g_candCount;
    if (n > CAND_CAP) n = CAND_CAP;
    unsigned p = blockIdx.x * 8u + (threadIdx.x >> 5);
    if (p >= n) return;
    int lid = threadIdx.x & 31;
    unsigned long long e = g_cand[p];
    unsigned idx = ~((unsigned)(e & 0xffffffffull));
    int a = idx % 9;
    int px = idx / 9;
    const float* wrow = wcls + a * 256;
    const float* rp = g_relu + px;
    double s = 0.0;
#pragma unroll
    for (int u = 0; u < 8; ++u) {
        int c = lid * 8 + u;
        s += (double)__ldg(wrow + c) * (double)__ldg(rp + (size_t)c * HW);
    }
#pragma unroll
    for (int off = 16; off > 0; off >>= 1)
        s += __shfl_down_sync(0xffffffffu, s, off);
    if (lid == 0) {
        s += (double)__ldg(bcls + a);
        unsigned key = f2k((float)s);
        g_cand[p] = ((unsigned long long)key << 32) | (unsigned)(~idx);
    }
}

// ---------------- single-block bitonic sort (descending) ----------------
__global__ void k_sort() {
    extern __shared__ unsigned long long ss[];
    int tid = threadIdx.x;
    unsigned n = g_candCount;
    if (n > CAND_CAP) n = CAND_CAP;
    for (int i = tid; i < CAND_CAP; i += 1024) ss[i] = (i < (int)n) ? g_cand[i] : 0ull;
    __syncthreads();
    for (unsigned k = 2; k <= (unsigned)CAND_CAP; k <<= 1) {
        for (unsigned j = k >> 1; j > 0; j >>= 1) {
            for (unsigned i = tid; i < (unsigned)CAND_CAP; i += 1024) {
                unsigned ixj = i ^ j;
                if (ixj > i) {
                    unsigned long long a = ss[i], b = ss[ixj];
                    bool sw = ((i & k) == 0u) ? (a < b) : (a > b);
                    if (sw) { ss[i] = b; ss[ixj] = a; }
                }
            }
            __syncthreads();
        }
    }
    for (int r = tid; r < PRE_NMS; r += 1024)
        g_topIdx[r] = ~((unsigned)(ss[r] & 0xffffffffull));
}

// ---------------- decode + clip + valid (no FMA contraction) ----------------
__global__ void k_decode(const int* __restrict__ imh, const int* __restrict__ imw) {
    int r = blockIdx.x * 256 + threadIdx.x;
    if (r >= PRE_NMS) return;
    unsigned idx = g_topIdx[r];
    int a = idx % 9;
    int p = idx / 9;
    int xx = p % FW;
    int yy = p / FW;
    int si = a / 3, ri = a - si * 3;
    double sc = (double)(32 << si);
    double rr = (ri == 0) ? 0.5 : ((ri == 1) ? 1.0 : 2.0);
    float hw = (float)(sc * sqrt(1.0 / rr) * 0.5);
    float hh = (float)(sc * sqrt(rr) * 0.5);
    float cx0 = __fmul_rn(__fadd_rn((float)xx, 0.5f), 4.0f);
    float cy0 = __fmul_rn(__fadd_rn((float)yy, 0.5f), 4.0f);
    float x1a = __fsub_rn(cx0, hw), x2a = __fadd_rn(cx0, hw);
    float y1a = __fsub_rn(cy0, hh), y2a = __fadd_rn(cy0, hh);
    float wa = __fsub_rn(x2a, x1a), ha = __fsub_rn(y2a, y1a);
    float cxa = __fadd_rn(x1a, __fmul_rn(0.5f, wa));
    float cya = __fadd_rn(y1a, __fmul_rn(0.5f, ha));
    float4 d = g_offs[idx];
    float cx = __fadd_rn(__fmul_rn(d.x, wa), cxa);
    float cy = __fadd_rn(__fmul_rn(d.y, ha), cya);
    float w = __fmul_rn(expf(d.z), wa);
    float h = __fmul_rn(expf(d.w), ha);
    float bw = (float)__ldg(imw);
    float bh = (float)__ldg(imh);
    float x1 = fminf(fmaxf(__fsub_rn(cx, __fmul_rn(0.5f, w)), 0.0f), bw);
    float y1 = fminf(fmaxf(__fsub_rn(cy, __fmul_rn(0.5f, h)), 0.0f), bh);
    float x2 = fminf(fmaxf(__fadd_rn(cx, __fmul_rn(0.5f, w)), 0.0f), bw);
    float y2 = fminf(fmaxf(__fadd_rn(cy, __fmul_rn(0.5f, h)), 0.0f), bh);
    float4 b; b.x = x1; b.y = y1; b.z = x2; b.w = y2;
    g_boxes[r] = b;
    bool valid = (__fsub_rn(x2, x1) >= 1.0f) && (__fsub_rn(y2, y1) >= 1.0f);
    if (valid) atomicOr(&g_validw[r >> 6], 1ull << (r & 63));
}

// ---------------- suppression bitmask matrix (no FMA contraction) ----------------
__global__ void k_sup() {
    __shared__ float4 bj[64];
    int t = threadIdx.x;
    int bjx = blockIdx.y;
    int j0 = bjx * 64;
    {
        int j = j0 + t;
        bj[t] = (j < PRE_NMS) ? g_boxes[j] : make_float4(0.f, 0.f, 0.f, 0.f);
    }
    __syncthreads();
    int i = blockIdx.x * 64 + t;
    if (i >= PRE_NMS) return;
    float4 A = g_boxes[i];
    float areaA = __fmul_rn(__fsub_rn(A.z, A.x), __fsub_rn(A.w, A.y));
    unsigned long long bits = 0ull;
    int jmax = PRE_NMS - j0;
    if (jmax > 64) jmax = 64;
    for (int jj = 0; jj < jmax; ++jj) {
        float4 B = bj[jj];
        float areaB = __fmul_rn(__fsub_rn(B.z, B.x), __fsub_rn(B.w, B.y));
        float lx = fmaxf(A.x, B.x), ly = fmaxf(A.y, B.y);
        float rx = fminf(A.z, B.z), ry = fminf(A.w, B.w);
        float iw = fmaxf(__fsub_rn(rx, lx), 0.0f);
        float ih = fmaxf(__fsub_rn(ry, ly), 0.0f);
        float inter = __fmul_rn(iw, ih);
        float denom = __fadd_rn(__fsub_rn(__fadd_rn(areaA, areaB), inter), 1e-9f);
        float iou = __fdiv_rn(inter, denom);
        if (iou > 0.7f) bits |= (1ull << jj);
    }
    g_sup[(size_t)i * NWORDS + bjx] = bits;
}

// ---------------- serial greedy NMS scan (1 warp, ring prefetch) ----------------
__global__ void k_scan() {
    int t = threadIdx.x;  // 0..31
    unsigned long long k0 = 0, k1 = 0, k2 = 0;
    unsigned long long v0 = g_validw[t];
    unsigned long long v1 = g_validw[t + 32];
    unsigned long long v2 = (t < 30) ? g_validw[t + 64] : 0ull;
    unsigned long long b0[8], b1[8], b2[8];
#pragma unroll
    for (int r = 0; r < 8; ++r) {
        const unsigned long long* row = g_sup + (size_t)r * NWORDS;
        b0[r] = row[t];
        b1[r] = row[t + 32];
        b2[r] = (t < 30) ? row[t + 64] : 0ull;
    }
#pragma unroll 1
    for (int base = 0; base < PRE_NMS; base += 8) {
#pragma unroll
        for (int s = 0; s < 8; ++s) {
            int i = base + s;
            unsigned long long vv = (b0[s] & k0) | (b1[s] & k1) | (b2[s] & k2);
            unsigned bal = __ballot_sync(0xffffffffu, vv != 0ull);
            int wi = i >> 6;
            if (bal == 0u) {
                unsigned long long bit = 1ull << (i & 63);
                if (wi < 32) {
                    if (t == wi && (v0 & bit)) k0 |= bit;
                } else if (wi < 64) {
                    if (t == (wi - 32) && (v1 & bit)) k1 |= bit;
                } else {
                    if (t == (wi - 64) && (v2 & bit)) k2 |= bit;
                }
            }
            int nr = i + 8;
            if (nr < PRE_NMS) {
                const unsigned long long* row = g_sup + (size_t)nr * NWORDS;
                b0[s] = row[t];
                b1[s] = row[t + 32];
                b2[s] = (t < 30) ? row[t + 64] : 0ull;
            }
        }
    }
    g_keepw[t] = k0;
    g_keepw[t + 32] = k1;
    if (t < 30) g_keepw[t + 64] = k2;
}

// ---------------- compact kept boxes into output ----------------
__global__ void k_out(float* __restrict__ out) {
    __shared__ unsigned pref[NWORDS];
    int tid = threadIdx.x;
    for (int i = tid; i < POST_NMS * 4; i += 256) out[i] = 0.0f;
    if (tid == 0) {
        unsigned run = 0;
        for (int w = 0; w < NWORDS; ++w) {
            pref[w] = run;
            run += (unsigned)__popcll(g_keepw[w]);
        }
    }
    __syncthreads();
    for (int i = tid; i < PRE_NMS; i += 256) {
        unsigned long long kw = g_keepw[i >> 6];
        if ((kw >> (i & 63)) & 1ull) {
            unsigned long long below = (i & 63) ? (kw & ((1ull << (i & 63)) - 1ull)) : 0ull;
            unsigned rank = pref[i >> 6] + (unsigned)__popcll(below);
            if (rank < POST_NMS) {
                float4 b = g_boxes[i];
                out[rank * 4 + 0] = b.x;
                out[rank * 4 + 1] = b.y;
                out[rank * 4 + 2] = b.z;
                out[rank * 4 + 3] = b.w;
            }
        }
    }
}

// ---------------- launch ----------------
extern "C" void kernel_launch(void* const* d_in, const int* in_sizes, int n_in,
                              void* d_out, int out_size) {
    const float* feat = (const float*)d_in[0];
    const float* w1 = (const float*)d_in[1];
    const float* b1 = (const float*)d_in[2];
    const float* wcls = (const float*)d_in[3];
    const float* bcls = (const float*)d_in[4];
    const float* wreg = (const float*)d_in[5];
    const float* breg = (const float*)d_in[6];
    const int* imh = (const int*)d_in[7];
    const int* imw = (const int*)d_in[8];
    float* out = (float*)d_out;

    cudaFuncSetAttribute(k_sort, cudaFuncAttributeMaxDynamicSharedMemorySize, 131072);

    k_zero<<<257, 256>>>();
    k_wt<<<KDIM, 256>>>(w1);
    k_conv1<<<dim3(HW / 128, 4), 256>>>(feat, b1);
    k_conv2<<<HW / 128, 128>>>(wcls, bcls, wreg, breg);
    k_thresh<<<1, 1024>>>();
    k_collect<<<(NANCH + 255) / 256, 256>>>();
    k_rescore<<<CAND_CAP / 8, 256>>>(wcls, bcls);
    k_sort<<<1, 1024, 131072>>>();
    k_decode<<<(PRE_NMS + 255) / 256, 256>>>(imh, imw);
    k_sup<<<dim3(NWORDS, NWORDS), 64>>>();
    k_scan<<<1, 32>>>();
    k_out<<<1, 256>>>(out);
}